// round 2
// baseline (speedup 1.0000x reference)
#include <cuda_runtime.h>

// ColorQuantizer: out[pix] = PALETTE[argmin_j | relu(x@W1+b1)@W2+b2 - c_j |]
// Shapes: x [32,3,512,512] f32, W1 [3,32], b1 [32], W2 [32,3], b2 [3].
// Output identical layout to x.
//
// The reference's straight-through estimator output == hard palette lookup.
// argmax(softmax(-dist/T)) == argmin(dist) == argmin(-2 p.c_j + |c_j|^2).

#define HW    262144      // 512*512
#define NQUAD 2097152     // 32*HW/4

// Palette is a compile-time constant of the problem (not an input).
#define PV(v) ((float)(v) / 255.0f * 2.0f - 1.0f)
#define P3(a,b,c) {PV(a), PV(b), PV(c)}
static __device__ constexpr float PAL[16][3] = {
    P3(0,0,0),       P3(255,255,255), P3(255,0,0),     P3(0,255,0),
    P3(0,0,255),     P3(255,255,0),   P3(255,0,255),   P3(0,255,255),
    P3(128,128,128), P3(128,0,0),     P3(0,128,0),     P3(0,0,128),
    P3(128,128,0),   P3(128,0,128),   P3(0,128,128),   P3(192,192,192)
};

// Rearranged weights: per hidden unit k, [W1[0][k], W1[1][k], W1[2][k], b1[k],
//                                         W2[k][0], W2[k][1], W2[k][2], 0]
__device__ float g_w[32 * 8];
__device__ float g_b2[4];

__global__ void prep_kernel(const float* __restrict__ W1, const float* __restrict__ b1,
                            const float* __restrict__ W2, const float* __restrict__ b2) {
    int k = threadIdx.x;
    if (k < 32) {
        g_w[k * 8 + 0] = W1[0 * 32 + k];
        g_w[k * 8 + 1] = W1[1 * 32 + k];
        g_w[k * 8 + 2] = W1[2 * 32 + k];
        g_w[k * 8 + 3] = b1[k];
        g_w[k * 8 + 4] = W2[k * 3 + 0];
        g_w[k * 8 + 5] = W2[k * 3 + 1];
        g_w[k * 8 + 6] = W2[k * 3 + 2];
        g_w[k * 8 + 7] = 0.0f;
    }
    if (k < 3) g_b2[k] = b2[k];
}

__global__ __launch_bounds__(256) void cq_kernel(const float* __restrict__ x,
                                                 float* __restrict__ out) {
    __shared__ float4 sW[64];          // 32 hidden units x 2 float4
    __shared__ float  spal[3][16];     // palette gather LUT (conflict-free: 16 banks)

    int tid = threadIdx.x;
    if (tid < 64) sW[tid] = reinterpret_cast<const float4*>(g_w)[tid];
    if (tid < 16) {
        spal[0][tid] = PAL[tid][0];
        spal[1][tid] = PAL[tid][1];
        spal[2][tid] = PAL[tid][2];
    }
    __syncthreads();

    unsigned q = blockIdx.x * 256u + tid;      // quad index, 4 consecutive pixels
    unsigned b = q >> 16;                      // batch = q / (HW/4)
    unsigned r = (q & 65535u) << 2;            // pixel offset within batch plane

    const float* base = x + (size_t)b * 3 * HW + r;
    float4 ch0 = *reinterpret_cast<const float4*>(base);
    float4 ch1 = *reinterpret_cast<const float4*>(base + HW);
    float4 ch2 = *reinterpret_cast<const float4*>(base + 2 * HW);

    float X0[4] = {ch0.x, ch0.y, ch0.z, ch0.w};
    float X1[4] = {ch1.x, ch1.y, ch1.z, ch1.w};
    float X2[4] = {ch2.x, ch2.y, ch2.z, ch2.w};
    float p0[4] = {0.f, 0.f, 0.f, 0.f};
    float p1[4] = {0.f, 0.f, 0.f, 0.f};
    float p2[4] = {0.f, 0.f, 0.f, 0.f};

    // MLP: p = relu(x @ W1 + b1) @ W2   (b2 added after the loop)
    #pragma unroll
    for (int k = 0; k < 32; k++) {
        float4 wa = sW[2 * k];       // W1 row-for-unit + b1
        float4 wb = sW[2 * k + 1];   // W2 row
        #pragma unroll
        for (int i = 0; i < 4; i++) {
            float a = fmaf(X0[i], wa.x, fmaf(X1[i], wa.y, fmaf(X2[i], wa.z, wa.w)));
            float h = fmaxf(a, 0.0f);
            p0[i] = fmaf(h, wb.x, p0[i]);
            p1[i] = fmaf(h, wb.y, p1[i]);
            p2[i] = fmaf(h, wb.z, p2[i]);
        }
    }

    float b2x = __ldg(&g_b2[0]);
    float b2y = __ldg(&g_b2[1]);
    float b2z = __ldg(&g_b2[2]);

    float r0[4], r1[4], r2[4];
    #pragma unroll
    for (int i = 0; i < 4; i++) {
        float q0 = p0[i] + b2x;
        float q1 = p1[i] + b2y;
        float q2 = p2[i] + b2z;

        // argmin_j  (-2 p . c_j + |c_j|^2); palette consts fold to immediates.
        int   bi   = 0;
        float best = 3.4e38f;
        #pragma unroll
        for (int j = 0; j < 16; j++) {
            const float m0  = -2.0f * PAL[j][0];
            const float m1  = -2.0f * PAL[j][1];
            const float m2  = -2.0f * PAL[j][2];
            const float csq = PAL[j][0] * PAL[j][0] + PAL[j][1] * PAL[j][1]
                            + PAL[j][2] * PAL[j][2];
            float s = fmaf(q0, m0, fmaf(q1, m1, fmaf(q2, m2, csq)));
            if (s < best) { best = s; bi = j; }   // strict <: first-index on ties
        }
        r0[i] = spal[0][bi];
        r1[i] = spal[1][bi];
        r2[i] = spal[2][bi];
    }

    float* obase = out + (size_t)b * 3 * HW + r;
    *reinterpret_cast<float4*>(obase)           = make_float4(r0[0], r0[1], r0[2], r0[3]);
    *reinterpret_cast<float4*>(obase + HW)      = make_float4(r1[0], r1[1], r1[2], r1[3]);
    *reinterpret_cast<float4*>(obase + 2 * HW)  = make_float4(r2[0], r2[1], r2[2], r2[3]);
}

extern "C" void kernel_launch(void* const* d_in, const int* in_sizes, int n_in,
                              void* d_out, int out_size) {
    const float* x  = (const float*)d_in[0];
    const float* W1 = (const float*)d_in[1];
    const float* b1 = (const float*)d_in[2];
    const float* W2 = (const float*)d_in[3];
    const float* b2 = (const float*)d_in[4];
    float* out = (float*)d_out;

    prep_kernel<<<1, 32>>>(W1, b1, W2, b2);
    cq_kernel<<<NQUAD / 256, 256>>>(x, out);
}